// round 2
// baseline (speedup 1.0000x reference)
#include <cuda_runtime.h>
#include <cmath>

#define TOKS 4096          // B_SZ * L
#define DD   1024          // D
#define NN   16            // N
#define ROWF ((2*DD + 1) * NN)   // 32784 floats per token in output

// scratch for phase-1 results (no cudaMalloc allowed)
__device__ float g_B[TOKS][NN];
__device__ float g_C[TOKS][NN];
__device__ float g_s[TOKS];

// ---------------------------------------------------------------------------
// Phase 1: projections  B = x @ Wb^T, C = x @ Wc^T, s = x @ Wd^T
// One warp handles a token PAIR (t, t+2048) to halve shared-weight traffic.
// Weights (33 rows x 1024) staged in shared (132 KB).
// ---------------------------------------------------------------------------
__global__ __launch_bounds__(512) void proj_kernel(
    const float* __restrict__ x, const float* __restrict__ Wb,
    const float* __restrict__ Wc, const float* __restrict__ Wd)
{
    extern __shared__ float4 sw[];   // 33 * 256 float4 = 135168 B
    for (int i = threadIdx.x; i < 33 * 256; i += blockDim.x) {
        int j = i >> 8, c = i & 255;
        float4 v;
        if (j < 16)      v = ((const float4*)Wb)[j * 256 + c];
        else if (j < 32) v = ((const float4*)Wc)[(j - 16) * 256 + c];
        else             v = ((const float4*)Wd)[c];
        sw[i] = v;
    }
    __syncthreads();

    int wg   = (blockIdx.x * blockDim.x + threadIdx.x) >> 5;  // 0..2047
    int lane = threadIdx.x & 31;
    int t0 = wg, t1 = wg + TOKS / 2;
    const float4* x0 = (const float4*)(x + (size_t)t0 * DD);
    const float4* x1 = (const float4*)(x + (size_t)t1 * DD);

    float acc0[33], acc1[33];
#pragma unroll
    for (int j = 0; j < 33; j++) { acc0[j] = 0.f; acc1[j] = 0.f; }

#pragma unroll
    for (int it = 0; it < 8; it++) {
        int c = it * 32 + lane;              // float4 index 0..255
        float4 a = __ldg(x0 + c);
        float4 b = __ldg(x1 + c);
#pragma unroll
        for (int j = 0; j < 33; j++) {
            float4 w = sw[j * 256 + c];
            acc0[j] = fmaf(a.x, w.x, fmaf(a.y, w.y, fmaf(a.z, w.z, fmaf(a.w, w.w, acc0[j]))));
            acc1[j] = fmaf(b.x, w.x, fmaf(b.y, w.y, fmaf(b.z, w.z, fmaf(b.w, w.w, acc1[j]))));
        }
    }

#pragma unroll
    for (int j = 0; j < 33; j++) {
#pragma unroll
        for (int o = 16; o > 0; o >>= 1) {
            acc0[j] += __shfl_xor_sync(0xffffffffu, acc0[j], o);
            acc1[j] += __shfl_xor_sync(0xffffffffu, acc1[j], o);
        }
    }

    if (lane == 0) {
#pragma unroll
        for (int j = 0; j < 16; j++) { g_B[t0][j] = acc0[j];      g_B[t1][j] = acc1[j]; }
#pragma unroll
        for (int j = 0; j < 16; j++) { g_C[t0][j] = acc0[16 + j]; g_C[t1][j] = acc1[16 + j]; }
        g_s[t0] = acc0[32];
        g_s[t1] = acc1[32];
    }
}

// ---------------------------------------------------------------------------
// Phase 2: the big elementwise expansion + 537 MB of streaming stores.
// A and 1/A staged in shared (128 KB) + delta_param (4 KB); 1 block/SM,
// grid-strided over tokens. Thread -> (d, n-quad): warp stores are 512B
// contiguous per STG.128 group.
//   A_bar      = exp(Delta * A[d,n])
//   deltaB_x   = (A_bar - 1) * (1/A[d,n]) * B[tok,n] * x[tok,d]   (Delta cancels)
// ---------------------------------------------------------------------------
__global__ __launch_bounds__(512) void ssm_kernel(
    const float* __restrict__ x, const float* __restrict__ A,
    const float* __restrict__ dparam, float* __restrict__ out)
{
    extern __shared__ float sm[];
    float* sA  = sm;                    // D*N
    float* sR  = sm + DD * NN;          // D*N  (1/A)
    float* sdp = sm + 2 * DD * NN;      // D

    for (int i = threadIdx.x; i < DD * NN; i += blockDim.x) {
        float a = A[i];
        sA[i] = a;
        sR[i] = __frcp_rn(a);
    }
    for (int i = threadIdx.x; i < DD; i += blockDim.x) sdp[i] = dparam[i];
    __syncthreads();

    const int q   = threadIdx.x & 3;    // n-quad 0..3
    const int dof = threadIdx.x >> 2;   // 0..127

    for (int tok = blockIdx.x; tok < TOKS; tok += gridDim.x) {
        float  s  = g_s[tok];
        float4 Bq = *((const float4*)g_B[tok] + q);
        const float* xr = x + (size_t)tok * DD;
        float* ob = out + (size_t)tok * ROWF;

        if (threadIdx.x < 4)
            __stcs((float4*)(ob + 2 * DD * NN) + threadIdx.x,
                   *((const float4*)g_C[tok] + threadIdx.x));

#pragma unroll
        for (int it = 0; it < 8; it++) {
            int d = dof + it * 128;
            float zz = s + sdp[d];
            // softplus == logaddexp(z, 0) == max(z,0) + log1p(exp(-|z|))
            float Delta = fmaxf(zz, 0.f) + log1pf(__expf(-fabsf(zz)));
            float xd = __ldg(xr + d);
            float4 a = ((const float4*)sA)[d * 4 + q];
            float4 r = ((const float4*)sR)[d * 4 + q];
            float4 eo, bo;
#define COMP(f)                                                              \
            {                                                                \
                float dA = Delta * a.f;                                      \
                float e  = __expf(dA);                                       \
                float em1 = (fabsf(dA) < 0.015625f)                          \
                    ? dA * fmaf(dA, fmaf(dA, 0.16666667f, 0.5f), 1.f)        \
                    : (e - 1.f);                                             \
                eo.f = e;                                                    \
                bo.f = em1 * r.f * (Bq.f * xd);                              \
            }
            COMP(x) COMP(y) COMP(z) COMP(w)
#undef COMP
            __stcs((float4*)ob + d * 4 + q, eo);
            __stcs((float4*)ob + DD * 4 + d * 4 + q, bo);
        }
    }
}

// ---------------------------------------------------------------------------
extern "C" void kernel_launch(void* const* d_in, const int* in_sizes, int n_in,
                              void* d_out, int out_size)
{
    const float* x  = (const float*)d_in[0];
    const float* Wb = (const float*)d_in[1];
    const float* Wc = (const float*)d_in[2];
    const float* Wd = (const float*)d_in[3];
    const float* A  = (const float*)d_in[4];
    const float* dp = (const float*)d_in[5];
    float* out = (float*)d_out;

    const int SMEM1 = 33 * 256 * 16;                   // 135168 B
    const int SMEM2 = (2 * DD * NN + DD) * 4;          // 135168 B
    cudaFuncSetAttribute(proj_kernel, cudaFuncAttributeMaxDynamicSharedMemorySize, SMEM1);
    cudaFuncSetAttribute(ssm_kernel,  cudaFuncAttributeMaxDynamicSharedMemorySize, SMEM2);

    // Phase 1: 2048 warps, one token-pair each (128 blocks x 512 threads)
    proj_kernel<<<128, 512, SMEM1>>>(x, Wb, Wc, Wd);
    // Phase 2: one resident block per SM (GB300 = 152 SMs), grid-strided tokens
    ssm_kernel<<<152, 512, SMEM2>>>(x, A, dp, out);
}